// round 7
// baseline (speedup 1.0000x reference)
#include <cuda_runtime.h>
#include <cstdint>

// OptimizedUniformSampler: KGE negative sampling + sorted-hash filter.
// R6: issue/ALU-bound per ncu -> IDIV removal (negs shift), branchless
// fixed-trip tree+tail bisect, 2-way interleaved searches for MLP.
// Output float32: neg [3T] then keep [T]. int64 inputs (verified R5);
// int32 fallback retained.

#define TREE_LVLS 12
#define TREE_SLOTS 4096
#define EPT 16
#define THREADS 256

__device__ int g_width;

__global__ void detect_kernel(const unsigned int* __restrict__ pw, int n_words) {
    if (threadIdx.x == 0) {
        int w = 8;
        int lim = n_words < 64 ? n_words : 64;
        for (int k = 1; k < lim; k += 2)
            if (pw[k] != 0u) { w = 4; break; }
        g_width = w;
    }
}

__global__ __launch_bounds__(THREADS)
void sampler_kernel(const void* __restrict__ posv,
                    const void* __restrict__ randv,
                    const void* __restrict__ hashv,
                    float* __restrict__ out,
                    int total, int negs_shift, int negs, int L,
                    int n_tail, long long keep_budget)
{
    __shared__ long long tree[TREE_SLOTS];
    const int W = g_width;
    const long long T = total;
    const int split = (total + 1) >> 1;
    const int base = blockIdx.x * (THREADS * EPT);

    // ---- build implicit bisect tree in smem ----
    for (int t = 1 + threadIdx.x; t < TREE_SLOTS; t += THREADS) {
        int msb = 31 - __clz(t);
        int lo = 0, hi = L;
        for (int b = msb - 1; b >= 0; b--) {
            if (lo >= hi) break;
            int mid = (lo + hi) >> 1;
            if ((t >> b) & 1) lo = mid + 1; else hi = mid;
        }
        long long v = 0x7fffffffffffffffLL;
        if (lo < hi) {
            int mid = (lo + hi) >> 1;
            v = (W == 8) ? __ldg(&((const long long*)hashv)[mid])
                         : (long long)__ldg(&((const int*)hashv)[mid]);
        }
        tree[t] = v;
    }
    __syncthreads();

    const bool full = (base + THREADS * EPT) <= total;

    if (W == 8 && full && negs_shift >= 0 && L >= TREE_SLOTS) {
        // ================= FAST PATH =================
        const long long* pos = (const long long*)posv;
        const long long* rnd = (const long long*)randv;
        const long long* hs  = (const long long*)hashv;

        #pragma unroll
        for (int j = 0; j < EPT; j += 2) {
            const int i0 = base + j * THREADS + threadIdx.x;
            const int i1 = i0 + THREADS;

            const int b0 = i0 >> negs_shift;
            const int b1 = i1 >> negs_shift;
            long long e00 = __ldg(&pos[(long long)b0 * 3 + 0]);
            long long r10 = __ldg(&pos[(long long)b0 * 3 + 1]);
            long long e20 = __ldg(&pos[(long long)b0 * 3 + 2]);
            long long e01 = __ldg(&pos[(long long)b1 * 3 + 0]);
            long long r11 = __ldg(&pos[(long long)b1 * 3 + 1]);
            long long e21 = __ldg(&pos[(long long)b1 * 3 + 2]);
            long long rv0 = __ldg(&rnd[i0]);
            long long rv1 = __ldg(&rnd[i1]);

            bool ch0 = (i0 < split), ch1 = (i1 < split);
            long long or0 = ch0 ? e00 : e20;
            long long or1 = ch1 ? e01 : e21;
            long long rp0 = rv0 + (((rv0 >= or0) && (or0 > 0)) ? 1LL : 0LL);
            long long rp1 = rv1 + (((rv1 >= or1) && (or1 > 0)) ? 1LL : 0LL);
            if (ch0) e00 = rp0; else e20 = rp0;
            if (ch1) e01 = rp1; else e21 = rp1;

            const long long h0 = (e00 << 42) | (r10 << 21) | e20;
            const long long h1 = (e01 << 42) | (r11 << 21) | e21;

            // convert triples to float now; frees 64-bit regs
            const float f00 = (float)e00, f10 = (float)r10, f20 = (float)e20;
            const float f01 = (float)e01, f11 = (float)r11, f21 = (float)e21;

            // ---- 12 fixed smem tree levels, branchless, 2-way ----
            int lo0 = 0, hi0 = L, n0 = 1;
            int lo1 = 0, hi1 = L, n1 = 1;
            #pragma unroll
            for (int lvl = 0; lvl < TREE_LVLS; lvl++) {
                const long long v0 = tree[n0];
                const long long v1 = tree[n1];
                const int m0 = (lo0 + hi0) >> 1;
                const int m1 = (lo1 + hi1) >> 1;
                const bool c0 = (v0 < h0);
                const bool c1 = (v1 < h1);
                lo0 = c0 ? m0 + 1 : lo0;  hi0 = c0 ? hi0 : m0;  n0 = 2 * n0 + (c0 ? 1 : 0);
                lo1 = c1 ? m1 + 1 : lo1;  hi1 = c1 ? hi1 : m1;  n1 = 2 * n1 + (c1 ? 1 : 0);
            }
            // ---- fixed n_tail global levels, branchless, 2-way ----
            for (int t = 0; t < n_tail; t++) {
                int m0 = (lo0 + hi0) >> 1;  m0 = m0 < L ? m0 : L - 1;
                int m1 = (lo1 + hi1) >> 1;  m1 = m1 < L ? m1 : L - 1;
                const long long v0 = __ldg(&hs[m0]);
                const long long v1 = __ldg(&hs[m1]);
                const bool a0 = lo0 < hi0, a1 = lo1 < hi1;
                const bool c0 = a0 && (v0 < h0);
                const bool c1 = a1 && (v1 < h1);
                lo0 = c0 ? m0 + 1 : lo0;  hi0 = (a0 && !c0) ? m0 : hi0;
                lo1 = c1 ? m1 + 1 : lo1;  hi1 = (a1 && !c1) ? m1 : hi1;
            }
            const int p0 = lo0 < L ? lo0 : L - 1;
            const int p1 = lo1 < L ? lo1 : L - 1;
            const bool in0 = (lo0 < L) && (__ldg(&hs[p0]) == h0);
            const bool in1 = (lo1 < L) && (__ldg(&hs[p1]) == h1);

            long long o0 = (long long)i0 * 3;
            long long o1 = (long long)i1 * 3;
            out[o0 + 0] = f00; out[o0 + 1] = f10; out[o0 + 2] = f20;
            out[o1 + 0] = f01; out[o1 + 1] = f11; out[o1 + 2] = f21;
            if ((long long)i0 < keep_budget) out[3 * T + i0] = in0 ? 0.0f : 1.0f;
            if ((long long)i1 < keep_budget) out[3 * T + i1] = in1 ? 0.0f : 1.0f;
        }
    } else {
        // ================= GENERIC PATH =================
        #pragma unroll 2
        for (int j = 0; j < EPT; j++) {
            int i = base + j * THREADS + threadIdx.x;
            if (i >= total) break;
            int b = i / negs;

            long long e0, r1, e2, rv;
            if (W == 8) {
                const long long* pos = (const long long*)posv;
                e0 = __ldg(&pos[(long long)b * 3 + 0]);
                r1 = __ldg(&pos[(long long)b * 3 + 1]);
                e2 = __ldg(&pos[(long long)b * 3 + 2]);
                rv = __ldg(&((const long long*)randv)[i]);
            } else {
                const int* pos = (const int*)posv;
                e0 = __ldg(&pos[b * 3 + 0]);
                r1 = __ldg(&pos[b * 3 + 1]);
                e2 = __ldg(&pos[b * 3 + 2]);
                rv = __ldg(&((const int*)randv)[i]);
            }
            bool chd = (i < split);
            long long orig = chd ? e0 : e2;
            long long repl = rv + (((rv >= orig) && (orig > 0)) ? 1LL : 0LL);
            if (chd) e0 = repl; else e2 = repl;

            long long h;
            if (W == 8) h = (e0 << 42) | (r1 << 21) | e2;
            else        h = (long long)(int)(((int)r1 << 21) | (int)e2);

            int lo = 0, hi = L, node = 1;
            #pragma unroll
            for (int lvl = 0; lvl < TREE_LVLS; lvl++) {
                if (lo >= hi || node >= TREE_SLOTS) break;
                int mid = (lo + hi) >> 1;
                if (tree[node] < h) { lo = mid + 1; node = 2 * node + 1; }
                else                { hi = mid;     node = 2 * node;     }
            }
            if (W == 8) {
                const long long* hsg = (const long long*)hashv;
                while (lo < hi) { int m = (lo + hi) >> 1;
                                  if (__ldg(&hsg[m]) < h) lo = m + 1; else hi = m; }
            } else {
                const int* hsg = (const int*)hashv;
                int h32 = (int)h;
                while (lo < hi) { int m = (lo + hi) >> 1;
                                  if (__ldg(&hsg[m]) < h32) lo = m + 1; else hi = m; }
            }
            bool in_set;
            if (W == 8) in_set = (lo < L) && (__ldg(&((const long long*)hashv)[lo]) == h);
            else        in_set = (lo < L) && (__ldg(&((const int*)hashv)[lo]) == (int)h);

            long long o = (long long)i * 3;
            out[o + 0] = (float)e0;
            out[o + 1] = (float)r1;
            out[o + 2] = (float)e2;
            if ((long long)i < keep_budget)
                out[3 * T + i] = in_set ? 0.0f : 1.0f;
        }
    }
}

extern "C" void kernel_launch(void* const* d_in, const int* in_sizes, int n_in,
                              void* d_out, int out_size) {
    int idx[3]; int cnt = 0;
    for (int k = 0; k < n_in && cnt < 3; k++)
        if (in_sizes[k] > 1) idx[cnt++] = k;
    for (int a = 0; a < cnt; a++)
        for (int c = a + 1; c < cnt; c++)
            if (in_sizes[idx[c]] < in_sizes[idx[a]]) { int t = idx[a]; idx[a] = idx[c]; idx[c] = t; }

    int i_pos = idx[0], i_hash = idx[1], i_rand = idx[2];
    const void* pos    = d_in[i_pos];
    const void* hashes = d_in[i_hash];
    const void* rv     = d_in[i_rand];

    int total = in_sizes[i_rand];
    int B     = in_sizes[i_pos] / 3;
    int L     = in_sizes[i_hash];
    int negs  = (B > 0) ? total / B : 1;
    if (negs < 1) negs = 1;

    // negs shift (-1 if not a power of two -> generic path)
    int negs_shift = -1;
    if ((negs & (negs - 1)) == 0) {
        negs_shift = 0;
        while ((1 << negs_shift) < negs) negs_shift++;
    }

    // fixed tail iteration count: max window after TREE_LVLS levels
    int maxwin = (L + TREE_SLOTS - 1) / TREE_SLOTS + 1;
    int n_tail = 0;
    while ((1 << n_tail) <= maxwin) n_tail++;

    long long T = total;
    long long oe = out_size;
    long long keep_budget = (oe >= 3 * T) ? (oe - 3 * T) : 0;
    if (keep_budget > T) keep_budget = T;

    detect_kernel<<<1, 32>>>((const unsigned int*)pos, in_sizes[i_pos]);

    int per_block = THREADS * EPT;
    int grid = (total + per_block - 1) / per_block;
    sampler_kernel<<<grid, THREADS>>>(pos, rv, hashes, (float*)d_out,
                                      total, negs_shift, negs, L,
                                      n_tail, keep_budget);
}

// round 8
// speedup vs baseline: 1.7123x; 1.7123x over previous
#include <cuda_runtime.h>
#include <cstdint>

// OptimizedUniformSampler: KGE negative sampling + sorted-hash filter.
// R8: wavefront-slot bound -> replace 20-probe binary search with a
// direct-index bucket table (2^19 buckets over (e0, r>>8)), membership-only
// scan of ~2.5 contiguous entries. Built per-launch, no atomics.
// Output float32: neg [3T] then keep [T].

#define THREADS 256
#define EPT 8
#define NB_BITS 19
#define NB (1 << NB_BITS)
#define EMPTY 0xFFFFFFFFu

__device__ int g_width;
__device__ int g_ok;
__device__ unsigned int g_bucket_lo[NB];   // 2 MB scratch

static __device__ __forceinline__ unsigned int bucket_of(long long h) {
    return (unsigned int)(((unsigned long long)h >> 42) << 2)
         | (unsigned int)(((unsigned long long)h >> 29) & 3ULL);
}

__global__ void detect_kernel(const unsigned int* __restrict__ pw, int n_words) {
    if (threadIdx.x == 0) {
        int w = 8;
        int lim = n_words < 64 ? n_words : 64;
        for (int k = 1; k < lim; k += 2)
            if (pw[k] != 0u) { w = 4; break; }
        g_width = w;
    }
}

__global__ void init_kernel() {
    int i = blockIdx.x * blockDim.x + threadIdx.x;
    if (i == 0) g_ok = 1;
    for (; i < NB; i += gridDim.x * blockDim.x)
        g_bucket_lo[i] = EMPTY;
}

__global__ void build_kernel(const long long* __restrict__ hs, int L) {
    if (g_width != 8) return;
    int i = blockIdx.x * blockDim.x + threadIdx.x;
    for (; i < L; i += gridDim.x * blockDim.x) {
        long long h = __ldg(&hs[i]);
        // structure validity: h must fit 59 bits, bits 31..41 must be zero
        if (((unsigned long long)h >> 59) != 0ULL ||
            (((unsigned long long)h >> 31) & 0x7FFULL) != 0ULL)
            g_ok = 0;
        unsigned int b = bucket_of(h) & (NB - 1);
        bool first = (i == 0);
        if (!first) {
            long long hp = __ldg(&hs[i - 1]);
            first = (bucket_of(hp) & (NB - 1)) != b;
        }
        if (first) g_bucket_lo[b] = (unsigned int)i;
    }
}

__global__ __launch_bounds__(THREADS)
void sampler_kernel(const void* __restrict__ posv,
                    const void* __restrict__ randv,
                    const void* __restrict__ hashv,
                    float* __restrict__ out,
                    int total, int negs_shift, int negs, int L,
                    long long keep_budget)
{
    const int W = g_width;
    const int OK = g_ok;
    const long long T = total;
    const int split = (total + 1) >> 1;
    const int base = blockIdx.x * (THREADS * EPT);
    const bool full = (base + THREADS * EPT) <= total;

    if (W == 8 && OK && full && negs_shift >= 0) {
        // ================= FAST PATH: bucket membership =================
        const long long* pos = (const long long*)posv;
        const long long* rnd = (const long long*)randv;
        const long long* hs  = (const long long*)hashv;

        #pragma unroll
        for (int j = 0; j < EPT; j += 2) {
            const int i0 = base + j * THREADS + threadIdx.x;
            const int i1 = i0 + THREADS;

            const int b0 = i0 >> negs_shift;
            const int b1 = i1 >> negs_shift;
            long long e00 = __ldg(&pos[(long long)b0 * 3 + 0]);
            long long r10 = __ldg(&pos[(long long)b0 * 3 + 1]);
            long long e20 = __ldg(&pos[(long long)b0 * 3 + 2]);
            long long e01 = __ldg(&pos[(long long)b1 * 3 + 0]);
            long long r11 = __ldg(&pos[(long long)b1 * 3 + 1]);
            long long e21 = __ldg(&pos[(long long)b1 * 3 + 2]);
            long long rv0 = __ldg(&rnd[i0]);
            long long rv1 = __ldg(&rnd[i1]);

            bool ch0 = (i0 < split), ch1 = (i1 < split);
            long long or0 = ch0 ? e00 : e20;
            long long or1 = ch1 ? e01 : e21;
            long long rp0 = rv0 + (((rv0 >= or0) && (or0 > 0)) ? 1LL : 0LL);
            long long rp1 = rv1 + (((rv1 >= or1) && (or1 > 0)) ? 1LL : 0LL);
            if (ch0) e00 = rp0; else e20 = rp0;
            if (ch1) e01 = rp1; else e21 = rp1;

            const long long h0 = (e00 << 42) | (r10 << 21) | e20;
            const long long h1 = (e01 << 42) | (r11 << 21) | e21;

            const unsigned int k0 = bucket_of(h0) & (NB - 1);
            const unsigned int k1 = bucket_of(h1) & (NB - 1);
            const unsigned int s0 = __ldg(&g_bucket_lo[k0]);
            const unsigned int s1 = __ldg(&g_bucket_lo[k1]);

            // contiguous scan: entries >= start are sorted; any entry of a
            // later bucket is > h, so the v>=h exit is always reached.
            bool in0 = false;
            if (s0 != EMPTY) {
                int idx = (int)s0;
                while (idx < L) {
                    long long v = __ldg(&hs[idx]);
                    if (v >= h0) { in0 = (v == h0); break; }
                    idx++;
                }
            }
            bool in1 = false;
            if (s1 != EMPTY) {
                int idx = (int)s1;
                while (idx < L) {
                    long long v = __ldg(&hs[idx]);
                    if (v >= h1) { in1 = (v == h1); break; }
                    idx++;
                }
            }

            long long o0 = (long long)i0 * 3;
            long long o1 = (long long)i1 * 3;
            out[o0 + 0] = (float)e00; out[o0 + 1] = (float)r10; out[o0 + 2] = (float)e20;
            out[o1 + 0] = (float)e01; out[o1 + 1] = (float)r11; out[o1 + 2] = (float)e21;
            if ((long long)i0 < keep_budget) out[3 * T + i0] = in0 ? 0.0f : 1.0f;
            if ((long long)i1 < keep_budget) out[3 * T + i1] = in1 ? 0.0f : 1.0f;
        }
    } else {
        // ================= GENERIC FALLBACK: plain bisect =================
        for (int j = 0; j < EPT; j++) {
            int i = base + j * THREADS + threadIdx.x;
            if (i >= total) break;
            int b = i / negs;

            long long e0, r1, e2, rv;
            if (W == 8) {
                const long long* pos = (const long long*)posv;
                e0 = __ldg(&pos[(long long)b * 3 + 0]);
                r1 = __ldg(&pos[(long long)b * 3 + 1]);
                e2 = __ldg(&pos[(long long)b * 3 + 2]);
                rv = __ldg(&((const long long*)randv)[i]);
            } else {
                const int* pos = (const int*)posv;
                e0 = __ldg(&pos[b * 3 + 0]);
                r1 = __ldg(&pos[b * 3 + 1]);
                e2 = __ldg(&pos[b * 3 + 2]);
                rv = __ldg(&((const int*)randv)[i]);
            }
            bool chd = (i < split);
            long long orig = chd ? e0 : e2;
            long long repl = rv + (((rv >= orig) && (orig > 0)) ? 1LL : 0LL);
            if (chd) e0 = repl; else e2 = repl;

            long long h;
            if (W == 8) h = (e0 << 42) | (r1 << 21) | e2;
            else        h = (long long)(int)(((int)r1 << 21) | (int)e2);

            int lo = 0, hi = L;
            if (W == 8) {
                const long long* hsg = (const long long*)hashv;
                while (lo < hi) { int m = (lo + hi) >> 1;
                                  if (__ldg(&hsg[m]) < h) lo = m + 1; else hi = m; }
            } else {
                const int* hsg = (const int*)hashv;
                int h32 = (int)h;
                while (lo < hi) { int m = (lo + hi) >> 1;
                                  if (__ldg(&hsg[m]) < h32) lo = m + 1; else hi = m; }
            }
            bool in_set;
            if (W == 8) in_set = (lo < L) && (__ldg(&((const long long*)hashv)[lo]) == h);
            else        in_set = (lo < L) && (__ldg(&((const int*)hashv)[lo]) == (int)h);

            long long o = (long long)i * 3;
            out[o + 0] = (float)e0;
            out[o + 1] = (float)r1;
            out[o + 2] = (float)e2;
            if ((long long)i < keep_budget)
                out[3 * T + i] = in_set ? 0.0f : 1.0f;
        }
    }
}

extern "C" void kernel_launch(void* const* d_in, const int* in_sizes, int n_in,
                              void* d_out, int out_size) {
    int idx[3]; int cnt = 0;
    for (int k = 0; k < n_in && cnt < 3; k++)
        if (in_sizes[k] > 1) idx[cnt++] = k;
    for (int a = 0; a < cnt; a++)
        for (int c = a + 1; c < cnt; c++)
            if (in_sizes[idx[c]] < in_sizes[idx[a]]) { int t = idx[a]; idx[a] = idx[c]; idx[c] = t; }

    int i_pos = idx[0], i_hash = idx[1], i_rand = idx[2];
    const void* pos    = d_in[i_pos];
    const void* hashes = d_in[i_hash];
    const void* rv     = d_in[i_rand];

    int total = in_sizes[i_rand];
    int B     = in_sizes[i_pos] / 3;
    int L     = in_sizes[i_hash];
    int negs  = (B > 0) ? total / B : 1;
    if (negs < 1) negs = 1;

    int negs_shift = -1;
    if ((negs & (negs - 1)) == 0) {
        negs_shift = 0;
        while ((1 << negs_shift) < negs) negs_shift++;
    }

    long long T = total;
    long long oe = out_size;
    long long keep_budget = (oe >= 3 * T) ? (oe - 3 * T) : 0;
    if (keep_budget > T) keep_budget = T;

    detect_kernel<<<1, 32>>>((const unsigned int*)pos, in_sizes[i_pos]);
    init_kernel<<<1024, THREADS>>>();
    build_kernel<<<2048, THREADS>>>((const long long*)hashes, L);

    int per_block = THREADS * EPT;
    int grid = (total + per_block - 1) / per_block;
    sampler_kernel<<<grid, THREADS>>>(pos, rv, hashes, (float*)d_out,
                                      total, negs_shift, negs, L, keep_budget);
}